// round 4
// baseline (speedup 1.0000x reference)
#include <cuda_runtime.h>
#include <math.h>

// Problem constants
#define BB 16
#define SS 512
#define DM 256
#define HH 8
#define DKV 32
#define CTXW 288   // DV*(H+1)
#define EPS 1e-5f

// -------- scratch (device globals; no allocation allowed) --------
__device__ float g_Q[BB * SS * DM];
__device__ float g_K[BB * SS * DM];
__device__ float g_V[BB * SS * DM];
__device__ float g_attn[(long)BB * HH * SS * SS];   // 134 MB
__device__ float g_vp2[BB * SS * DKV];
__device__ float g_ctx[BB * SS * CTXW];
__device__ float g_fc[BB * SS * DM];

// ============================================================
// Generic tiled SGEMM: C[M,N] = A[M,K] @ B[K,N], row-major, batched
// block 16x16, tile 64x64x16, 4x4 register blocking
// ============================================================
__global__ __launch_bounds__(256) void sgemm_kernel(
    const float* __restrict__ A, const float* __restrict__ B, float* __restrict__ C,
    int M, int N, int K, int lda, int ldb, int ldc,
    long long sA, long long sB, long long sC)
{
    int bz = blockIdx.z;
    A += bz * sA; B += bz * sB; C += bz * sC;

    __shared__ float As[16][65];  // As[k][m]
    __shared__ float Bs[16][65];  // Bs[k][n]

    int tx = threadIdx.x, ty = threadIdx.y;
    int tid = ty * 16 + tx;
    int m0 = blockIdx.y * 64, n0 = blockIdx.x * 64;

    float acc[4][4] = {};

    for (int k0 = 0; k0 < K; k0 += 16) {
        for (int i = tid; i < 64 * 16; i += 256) {
            int m = i >> 4, kk = i & 15;
            float v = 0.f;
            if (m0 + m < M && k0 + kk < K) v = A[(long long)(m0 + m) * lda + k0 + kk];
            As[kk][m] = v;
        }
        for (int i = tid; i < 16 * 64; i += 256) {
            int kk = i >> 6, n = i & 63;
            float v = 0.f;
            if (k0 + kk < K && n0 + n < N) v = B[(long long)(k0 + kk) * ldb + n0 + n];
            Bs[kk][n] = v;
        }
        __syncthreads();
#pragma unroll
        for (int kk = 0; kk < 16; kk++) {
            float a[4], b[4];
#pragma unroll
            for (int i = 0; i < 4; i++) a[i] = As[kk][ty * 4 + i];
#pragma unroll
            for (int j = 0; j < 4; j++) b[j] = Bs[kk][tx * 4 + j];
#pragma unroll
            for (int i = 0; i < 4; i++)
#pragma unroll
                for (int j = 0; j < 4; j++) acc[i][j] += a[i] * b[j];
        }
        __syncthreads();
    }
#pragma unroll
    for (int i = 0; i < 4; i++) {
        int m = m0 + ty * 4 + i;
        if (m >= M) continue;
#pragma unroll
        for (int j = 0; j < 4; j++) {
            int n = n0 + tx * 4 + j;
            if (n < N) C[(long long)m * ldc + n] = acc[i][j];
        }
    }
}

// ============================================================
// Fused attention: scores -> mask -> softmax -> (write attn) -> attn@V
// grid (S/16, H, B), block 256.  Static smem ~43 KB.
// ============================================================
__global__ __launch_bounds__(256) void attn_kernel(
    const float* __restrict__ Q, const float* __restrict__ K, const float* __restrict__ V,
    const int* __restrict__ mask, float* __restrict__ attn, float* __restrict__ ctx)
{
    const int q0 = blockIdx.x * 16;
    const int h = blockIdx.y;
    const int b = blockIdx.z;
    const int tid = threadIdx.x;

    __shared__ float Qs[16][33];
    __shared__ float Sb[16][512];
    __shared__ float KVs[64][33];

    // load Q tile, pre-scaled by 1/sqrt(DK)
    for (int i = tid; i < 16 * 32; i += 256) {
        int qq = i >> 5, d = i & 31;
        Qs[qq][d] = Q[((long long)(b * SS + q0 + qq)) * DM + h * DKV + d] * 0.17677669529663687f;
    }
    __syncthreads();

    // ---- scores + mask ----
    const long long mrow0 = (((long long)(b * HH + h)) * SS + q0) * SS;
    for (int k0 = 0; k0 < SS; k0 += 64) {
        for (int i = tid; i < 64 * 32; i += 256) {
            int kk = i >> 5, d = i & 31;
            KVs[kk][d] = K[((long long)(b * SS + k0 + kk)) * DM + h * DKV + d];
        }
        __syncthreads();
        int kk = tid & 63;
        int qb = tid >> 6;  // 0..3
#pragma unroll
        for (int r = 0; r < 4; r++) {
            int qq = qb * 4 + r;
            float s = 0.f;
#pragma unroll
            for (int d = 0; d < 32; d++) s += Qs[qq][d] * KVs[kk][d];
            int mk = mask[mrow0 + (long long)qq * SS + k0 + kk];
            Sb[qq][k0 + kk] = mk ? -1e9f : s;
        }
        __syncthreads();
    }

    // ---- softmax per row (8 warps x 2 rows), write attn ----
    int warp = tid >> 5, lane = tid & 31;
    for (int rr = 0; rr < 2; rr++) {
        int qq = warp * 2 + rr;
        float mx = -1e30f;
        for (int j = lane; j < SS; j += 32) mx = fmaxf(mx, Sb[qq][j]);
#pragma unroll
        for (int o = 16; o; o >>= 1) mx = fmaxf(mx, __shfl_xor_sync(0xffffffffu, mx, o));
        float sum = 0.f;
        for (int j = lane; j < SS; j += 32) {
            float e = __expf(Sb[qq][j] - mx);
            Sb[qq][j] = e;
            sum += e;
        }
#pragma unroll
        for (int o = 16; o; o >>= 1) sum += __shfl_xor_sync(0xffffffffu, sum, o);
        float inv = 1.f / sum;
        long long base = mrow0 + (long long)qq * SS;
        for (int j = lane; j < SS; j += 32) {
            float a = Sb[qq][j] * inv;
            Sb[qq][j] = a;
            attn[base + j] = a;
        }
    }
    __syncthreads();

    // ---- attn @ V ----
    float acc0 = 0.f, acc1 = 0.f;
    int d = tid & 31;
    int qr = tid >> 5;  // rows qr and qr+8
    for (int k0 = 0; k0 < SS; k0 += 64) {
        for (int i = tid; i < 64 * 32; i += 256) {
            int kk = i >> 5, dd = i & 31;
            KVs[kk][dd] = V[((long long)(b * SS + k0 + kk)) * DM + h * DKV + dd];
        }
        __syncthreads();
#pragma unroll
        for (int kk = 0; kk < 64; kk++) {
            float vv = KVs[kk][d];
            acc0 += Sb[qr][k0 + kk] * vv;
            acc1 += Sb[qr + 8][k0 + kk] * vv;
        }
        __syncthreads();
    }
    ctx[((long long)(b * SS + q0 + qr)) * CTXW + h * DKV + d] = acc0;
    ctx[((long long)(b * SS + q0 + qr + 8)) * CTXW + h * DKV + d] = acc1;
}

// ============================================================
// Gate: per (b,i,j): v = [matrix[b,j,i], attn[b,:,j,i]] (9 ch),
// LN -> relu(9->6) -> sigmoid(6->1); matrix_out = matrix * g
// grid (S/32, S/32, B), block 256
// ============================================================
__global__ __launch_bounds__(256) void gate_kernel(
    const float* __restrict__ attn, const float* __restrict__ matrix, float* __restrict__ mout,
    const float* __restrict__ fu_ln_g, const float* __restrict__ fu_ln_b,
    const float* __restrict__ fu_w1, const float* __restrict__ fu_b1,
    const float* __restrict__ fu_w2, const float* __restrict__ fu_b2)
{
    __shared__ float pl[9][32][33];
    __shared__ float pg[9], pb[9], w1[9][6], b1[6], w2[6], b2s;

    int b = blockIdx.z;
    int i0 = blockIdx.y * 32, j0 = blockIdx.x * 32;
    int tid = threadIdx.x;

    if (tid < 9) { pg[tid] = fu_ln_g[tid]; pb[tid] = fu_ln_b[tid]; }
    if (tid >= 32 && tid < 86) { int t = tid - 32; w1[t / 6][t % 6] = fu_w1[t]; }
    if (tid >= 96 && tid < 102) b1[tid - 96] = fu_b1[tid - 96];
    if (tid >= 128 && tid < 134) w2[tid - 128] = fu_w2[tid - 128];
    if (tid == 160) b2s = fu_b2[0];

    // planes: pl[c][jj][ii] = (c==0 ? matrix : attn[h=c-1])[b, j0+jj, i0+ii]
    for (int c = 0; c < 9; c++) {
        const float* src = (c == 0) ? (matrix + (long long)b * SS * SS)
                                    : (attn + ((long long)(b * HH + c - 1)) * SS * SS);
        for (int i = tid; i < 1024; i += 256) {
            int jj = i >> 5, ii = i & 31;
            pl[c][jj][ii] = src[(long long)(j0 + jj) * SS + i0 + ii];
        }
    }
    __syncthreads();

#pragma unroll
    for (int r = 0; r < 4; r++) {
        int idx = tid + r * 256;
        int ii = idx >> 5, jj = idx & 31;  // jj fastest -> coalesced writes
        float v[9];
        float m = 0.f;
#pragma unroll
        for (int c = 0; c < 9; c++) { v[c] = pl[c][jj][ii]; m += v[c]; }
        m *= (1.f / 9.f);
        float var = 0.f;
#pragma unroll
        for (int c = 0; c < 9; c++) { float dd = v[c] - m; var += dd * dd; }
        var *= (1.f / 9.f);
        float rinv = rsqrtf(var + EPS);
        float y[9];
#pragma unroll
        for (int c = 0; c < 9; c++) y[c] = pg[c] * (v[c] - m) * rinv + pb[c];
        float z = b2s;
#pragma unroll
        for (int j = 0; j < 6; j++) {
            float t = b1[j];
#pragma unroll
            for (int c = 0; c < 9; c++) t += y[c] * w1[c][j];
            t = fmaxf(t, 0.f);
            z += t * w2[j];
        }
        float g = 1.f / (1.f + __expf(-z));
        long long o = ((long long)b * SS + i0 + ii) * SS + j0 + jj;
        mout[o] = matrix[o] * g;
    }
}

// ============================================================
// Final layernorm over 256 channels: one block per row
// ============================================================
__global__ __launch_bounds__(256) void ln_kernel(
    const float* __restrict__ x, const float* __restrict__ g,
    const float* __restrict__ bt, float* __restrict__ out)
{
    int row = blockIdx.x, tid = threadIdx.x;
    float v = x[(long long)row * DM + tid];

    __shared__ float red[8];
    float s = v;
#pragma unroll
    for (int o = 16; o; o >>= 1) s += __shfl_xor_sync(0xffffffffu, s, o);
    if ((tid & 31) == 0) red[tid >> 5] = s;
    __syncthreads();
    float tot = 0.f;
#pragma unroll
    for (int i = 0; i < 8; i++) tot += red[i];
    float m = tot * (1.f / DM);
    __syncthreads();

    float d = v - m;
    float s2 = d * d;
#pragma unroll
    for (int o = 16; o; o >>= 1) s2 += __shfl_xor_sync(0xffffffffu, s2, o);
    if ((tid & 31) == 0) red[tid >> 5] = s2;
    __syncthreads();
    float vtot = 0.f;
#pragma unroll
    for (int i = 0; i < 8; i++) vtot += red[i];
    float var = vtot * (1.f / DM);

    out[(long long)row * DM + tid] = g[tid] * d * rsqrtf(var + EPS) + bt[tid];
}

// ============================================================
extern "C" void kernel_launch(void* const* d_in, const int* in_sizes, int n_in,
                              void* d_out, int out_size)
{
    const float* inQ    = (const float*)d_in[0];
    const float* inK    = (const float*)d_in[1];
    const float* inV    = (const float*)d_in[2];
    const int*   mask   = (const int*)  d_in[3];   // bool -> 4-byte; nonzero test works for int32/float32
    const float* matrix = (const float*)d_in[4];
    const float* W_Q    = (const float*)d_in[5];
    const float* W_K    = (const float*)d_in[6];
    const float* W_V    = (const float*)d_in[7];
    const float* W_V2   = (const float*)d_in[8];
    const float* W_fc   = (const float*)d_in[9];
    const float* ln_g   = (const float*)d_in[10];
    const float* ln_b   = (const float*)d_in[11];
    const float* fu_ln_g= (const float*)d_in[12];
    const float* fu_ln_b= (const float*)d_in[13];
    const float* fu_w1  = (const float*)d_in[14];
    const float* fu_b1  = (const float*)d_in[15];
    const float* fu_w2  = (const float*)d_in[16];
    const float* fu_b2  = (const float*)d_in[17];

    float* out  = (float*)d_out;                       // [B,S,DM]
    float* mout = (float*)d_out + (long long)BB * SS * DM;  // [B,S,S]

    float *pQ, *pK, *pV, *pattn, *pvp2, *pctx, *pfc;
    cudaGetSymbolAddress((void**)&pQ, g_Q);
    cudaGetSymbolAddress((void**)&pK, g_K);
    cudaGetSymbolAddress((void**)&pV, g_V);
    cudaGetSymbolAddress((void**)&pattn, g_attn);
    cudaGetSymbolAddress((void**)&pvp2, g_vp2);
    cudaGetSymbolAddress((void**)&pctx, g_ctx);
    cudaGetSymbolAddress((void**)&pfc, g_fc);

    const int M = BB * SS;  // 8192
    dim3 blk(16, 16);

    // QKV projections: [8192,256] @ [256,256]
    sgemm_kernel<<<dim3(4, 128, 1), blk>>>(inQ, W_Q, pQ, M, DM, DM, DM, DM, DM, 0, 0, 0);
    sgemm_kernel<<<dim3(4, 128, 1), blk>>>(inK, W_K, pK, M, DM, DM, DM, DM, DM, 0, 0, 0);
    sgemm_kernel<<<dim3(4, 128, 1), blk>>>(inV, W_V, pV, M, DM, DM, DM, DM, DM, 0, 0, 0);
    // Vp2 = input_V @ W_V2 : [8192,256] @ [256,32]
    sgemm_kernel<<<dim3(1, 128, 1), blk>>>(inV, W_V2, pvp2, M, DKV, DM, DM, DKV, DKV, 0, 0, 0);

    // fused attention (writes attn + ctx columns 0..255)
    attn_kernel<<<dim3(SS / 16, HH, BB), 256>>>(pQ, pK, pV, mask, pattn, pctx);

    // context2 = matrix @ Vp2 (batched), into ctx columns 256..287
    // FIX (R3): column offset is H*DV = 256 (was DM*HH = 2048 — wrote context2
    // 7 rows + 32 cols off, corrupting the fc input => rel_err 1.41)
    sgemm_kernel<<<dim3(1, 8, BB), blk>>>(matrix, pvp2, pctx + HH * DKV,
                                          SS, DKV, SS, SS, DKV, CTXW,
                                          (long long)SS * SS, (long long)SS * DKV,
                                          (long long)SS * CTXW);

    // gate -> matrix_out
    gate_kernel<<<dim3(SS / 32, SS / 32, BB), 256>>>(pattn, matrix, mout,
                                                     fu_ln_g, fu_ln_b, fu_w1, fu_b1, fu_w2, fu_b2);

    // fc: [8192,288] @ [288,256]
    sgemm_kernel<<<dim3(4, 128, 1), blk>>>(pctx, W_fc, pfc, M, DM, CTXW, CTXW, DM, DM, 0, 0, 0);

    // final layernorm -> output
    ln_kernel<<<M, 256>>>(pfc, ln_g, ln_b, out);
}

// round 5
// speedup vs baseline: 1.3442x; 1.3442x over previous
#include <cuda_runtime.h>
#include <math.h>

// Problem constants
#define BB 16
#define SS 512
#define DM 256
#define HH 8
#define DKV 32
#define CTXW 288   // DV*(H+1)
#define EPS 1e-5f

// -------- scratch (device globals; no allocation allowed) --------
__device__ float g_Q[BB * SS * DM];
__device__ float g_K[BB * SS * DM];
__device__ float g_V[BB * SS * DM];
__device__ float g_attn[(long)BB * HH * SS * SS];   // 134 MB
__device__ float g_vp2[BB * SS * DKV];
__device__ float g_ctx[BB * SS * CTXW];
__device__ float g_fc[BB * SS * DM];

// ---- packed f32x2 FMA (Blackwell FFMA2; PTX-only, ptxas won't auto-fuse) ----
__device__ __forceinline__ void ffma2(float2 &d, const float2 &a, const float2 &b) {
    unsigned long long &dd = reinterpret_cast<unsigned long long &>(d);
    const unsigned long long &aa = reinterpret_cast<const unsigned long long &>(a);
    const unsigned long long &bb = reinterpret_cast<const unsigned long long &>(b);
    asm("fma.rn.f32x2 %0, %1, %2, %0;" : "+l"(dd) : "l"(aa), "l"(bb));
}

// ============================================================
// SGEMM v2: C[M,N] = A[M,K] @ B[K,N] row-major, tile 128x64, BK=16
// 256 threads, per-thread 8x4 outputs as 4 m-pairs x 4 cols (FFMA2)
// All launched shapes divide tiles exactly; no guards.
// ============================================================
__global__ __launch_bounds__(256) void sgemm2_kernel(
    const float* __restrict__ A, const float* __restrict__ B, float* __restrict__ C,
    int K, int lda, int ldb, int ldc)
{
    __shared__ __align__(16) float As[16][130];  // [k][m], m contiguous
    __shared__ __align__(16) float Bs[16][68];   // [k][n]
    const int tid = threadIdx.x;
    const int tx = tid & 15, ty = tid >> 4;
    const int m0 = blockIdx.y * 128, n0 = blockIdx.x * 64;

    float2 acc[4][4];
#pragma unroll
    for (int i = 0; i < 4; i++)
#pragma unroll
        for (int j = 0; j < 4; j++) acc[i][j] = make_float2(0.f, 0.f);

    for (int k0 = 0; k0 < K; k0 += 16) {
#pragma unroll
        for (int t = 0; t < 2; t++) {
            int idx = tid + t * 256;              // 0..511 float4 slots (128 rows x 4)
            int row = idx >> 2, kq = idx & 3;
            float4 v = *(const float4*)&A[(size_t)(m0 + row) * lda + k0 + kq * 4];
            As[kq * 4 + 0][row] = v.x; As[kq * 4 + 1][row] = v.y;
            As[kq * 4 + 2][row] = v.z; As[kq * 4 + 3][row] = v.w;
        }
        {
            int kk = tid >> 4, nq = tid & 15;
            *(float4*)&Bs[kk][nq * 4] =
                *(const float4*)&B[(size_t)(k0 + kk) * ldb + n0 + nq * 4];
        }
        __syncthreads();
#pragma unroll
        for (int kk = 0; kk < 16; kk++) {
            float2 a[4];
#pragma unroll
            for (int i = 0; i < 4; i++) a[i] = *(float2*)&As[kk][ty * 8 + 2 * i];
            float2 bA = *(float2*)&Bs[kk][tx * 4];
            float2 bB = *(float2*)&Bs[kk][tx * 4 + 2];
            float2 bj[4] = {{bA.x, bA.x}, {bA.y, bA.y}, {bB.x, bB.x}, {bB.y, bB.y}};
#pragma unroll
            for (int j = 0; j < 4; j++)
#pragma unroll
                for (int i = 0; i < 4; i++) ffma2(acc[i][j], a[i], bj[j]);
        }
        __syncthreads();
    }
#pragma unroll
    for (int i = 0; i < 4; i++) {
        int m = m0 + ty * 8 + 2 * i;
        float4 lo = {acc[i][0].x, acc[i][1].x, acc[i][2].x, acc[i][3].x};
        float4 hi = {acc[i][0].y, acc[i][1].y, acc[i][2].y, acc[i][3].y};
        *(float4*)&C[(size_t)m * ldc + n0 + tx * 4] = lo;
        *(float4*)&C[(size_t)(m + 1) * ldc + n0 + tx * 4] = hi;
    }
}

// ============================================================
// SGEMM narrow: N=32 (vp2 projection). tile 128x32, BK=16.
// ============================================================
__global__ __launch_bounds__(256) void sgemm_n32_kernel(
    const float* __restrict__ A, const float* __restrict__ B, float* __restrict__ C,
    int K, int lda)
{
    __shared__ __align__(16) float As[16][130];
    __shared__ __align__(16) float Bs[16][36];
    const int tid = threadIdx.x;
    const int tx = tid & 7, ty = tid >> 3;   // 8 col-groups x 32 row-groups
    const int m0 = blockIdx.y * 128;

    float2 acc[2][4];
#pragma unroll
    for (int i = 0; i < 2; i++)
#pragma unroll
        for (int j = 0; j < 4; j++) acc[i][j] = make_float2(0.f, 0.f);

    for (int k0 = 0; k0 < K; k0 += 16) {
#pragma unroll
        for (int t = 0; t < 2; t++) {
            int idx = tid + t * 256;
            int row = idx >> 2, kq = idx & 3;
            float4 v = *(const float4*)&A[(size_t)(m0 + row) * lda + k0 + kq * 4];
            As[kq * 4 + 0][row] = v.x; As[kq * 4 + 1][row] = v.y;
            As[kq * 4 + 2][row] = v.z; As[kq * 4 + 3][row] = v.w;
        }
        if (tid < 128) {
            int kk = tid >> 3, nq = tid & 7;
            *(float4*)&Bs[kk][nq * 4] =
                *(const float4*)&B[(size_t)(k0 + kk) * DKV + nq * 4];
        }
        __syncthreads();
#pragma unroll
        for (int kk = 0; kk < 16; kk++) {
            float2 a0 = *(float2*)&As[kk][ty * 4];
            float2 a1 = *(float2*)&As[kk][ty * 4 + 2];
            float2 bA = *(float2*)&Bs[kk][tx * 4];
            float2 bB = *(float2*)&Bs[kk][tx * 4 + 2];
            float2 bj[4] = {{bA.x, bA.x}, {bA.y, bA.y}, {bB.x, bB.x}, {bB.y, bB.y}};
#pragma unroll
            for (int j = 0; j < 4; j++) { ffma2(acc[0][j], a0, bj[j]); ffma2(acc[1][j], a1, bj[j]); }
        }
        __syncthreads();
    }
#pragma unroll
    for (int i = 0; i < 2; i++) {
        int m = m0 + ty * 4 + 2 * i;
        float4 lo = {acc[i][0].x, acc[i][1].x, acc[i][2].x, acc[i][3].x};
        float4 hi = {acc[i][0].y, acc[i][1].y, acc[i][2].y, acc[i][3].y};
        *(float4*)&C[(size_t)m * DKV + tx * 4] = lo;
        *(float4*)&C[(size_t)(m + 1) * DKV + tx * 4] = hi;
    }
}

// ============================================================
// Fused attention v2: Q in registers, packed FFMA2 scores / AV,
// float4 softmax + attn write. grid (S/16, H, B), 256 threads.
// ============================================================
__global__ __launch_bounds__(256) void attn2_kernel(
    const float* __restrict__ Q, const float* __restrict__ K, const float* __restrict__ V,
    const int* __restrict__ mask, float* __restrict__ attn, float* __restrict__ ctx)
{
    const int q0 = blockIdx.x * 16;
    const int h = blockIdx.y;
    const int b = blockIdx.z;
    const int tid = threadIdx.x;
    const int lane = tid & 31, warp = tid >> 5;

    __shared__ __align__(16) float  Sb[16][528];     // stride 528: bank-shifted rows
    __shared__ __align__(16) float2 KV2[64][17];     // K/V chunk (also Q staging)

    // ---- stage Q scaled, then pull own row into registers ----
    {
        int sq = tid >> 4, dp = tid & 15;
        float2 v = *(const float2*)&Q[((size_t)(b * SS + q0 + sq)) * DM + h * DKV + dp * 2];
        v.x *= 0.17677669529663687f; v.y *= 0.17677669529663687f;
        KV2[sq][dp] = v;
    }
    __syncthreads();
    const int qq = (warp << 1) | (lane >> 4);
    float2 qr[16];
#pragma unroll
    for (int dp = 0; dp < 16; dp++) qr[dp] = KV2[qq][dp];
    __syncthreads();

    const long long mrow0 = (((long long)(b * HH + h)) * SS + q0) * SS;

    // ---- scores + mask ----
    for (int k0 = 0; k0 < SS; k0 += 64) {
#pragma unroll
        for (int t = 0; t < 4; t++) {
            int idx = tid + t * 256, kk = idx >> 4, dp = idx & 15;
            KV2[kk][dp] = *(const float2*)&K[((size_t)(b * SS + k0 + kk)) * DM + h * DKV + dp * 2];
        }
        __syncthreads();
        int kb = lane & 15;
#pragma unroll
        for (int jj = 0; jj < 4; jj++) {
            int kk = kb + jj * 16;
            float2 acc = make_float2(0.f, 0.f);
#pragma unroll
            for (int dp = 0; dp < 16; dp++) ffma2(acc, qr[dp], KV2[kk][dp]);
            float s = acc.x + acc.y;
            int mk = mask[mrow0 + (long long)qq * SS + k0 + kk];
            Sb[qq][k0 + kk] = mk ? -1e9f : s;
        }
        __syncthreads();
    }

    // ---- softmax (warp-local rows 2w, 2w+1) + write attn ----
#pragma unroll
    for (int rr = 0; rr < 2; rr++) {
        int q = (warp << 1) | rr;
        float mx = -1e30f;
#pragma unroll
        for (int t = 0; t < 4; t++) {
            float4 v = *(float4*)&Sb[q][(lane + t * 32) * 4];
            mx = fmaxf(mx, fmaxf(fmaxf(v.x, v.y), fmaxf(v.z, v.w)));
        }
#pragma unroll
        for (int o = 16; o; o >>= 1) mx = fmaxf(mx, __shfl_xor_sync(0xffffffffu, mx, o));
        float sum = 0.f;
#pragma unroll
        for (int t = 0; t < 4; t++) {
            float4 v = *(float4*)&Sb[q][(lane + t * 32) * 4];
            v.x = __expf(v.x - mx); v.y = __expf(v.y - mx);
            v.z = __expf(v.z - mx); v.w = __expf(v.w - mx);
            *(float4*)&Sb[q][(lane + t * 32) * 4] = v;
            sum += v.x + v.y + v.z + v.w;
        }
#pragma unroll
        for (int o = 16; o; o >>= 1) sum += __shfl_xor_sync(0xffffffffu, sum, o);
        float inv = 1.f / sum;
        long long base = mrow0 + (long long)q * SS;
#pragma unroll
        for (int t = 0; t < 4; t++) {
            float4 v = *(float4*)&Sb[q][(lane + t * 32) * 4];
            v.x *= inv; v.y *= inv; v.z *= inv; v.w *= inv;
            *(float4*)&Sb[q][(lane + t * 32) * 4] = v;
            *(float4*)&attn[base + (lane + t * 32) * 4] = v;
        }
    }

    // ---- attn @ V ----
    {
        const int cq = tid >> 4, dp = tid & 15;   // cq == qq mapping (warp-local Sb rows)
        float2 acc = make_float2(0.f, 0.f);
        for (int k0 = 0; k0 < SS; k0 += 64) {
#pragma unroll
            for (int t = 0; t < 4; t++) {
                int idx = tid + t * 256, kk = idx >> 4, dq = idx & 15;
                KV2[kk][dq] = *(const float2*)&V[((size_t)(b * SS + k0 + kk)) * DM + h * DKV + dq * 2];
            }
            __syncthreads();
#pragma unroll
            for (int kp = 0; kp < 32; kp++) {
                float2 ap = *(const float2*)&Sb[cq][k0 + 2 * kp];
                float2 a0 = {ap.x, ap.x}, a1 = {ap.y, ap.y};
                ffma2(acc, a0, KV2[2 * kp][dp]);
                ffma2(acc, a1, KV2[2 * kp + 1][dp]);
            }
            __syncthreads();
        }
        *(float2*)&ctx[((size_t)(b * SS + q0 + cq)) * CTXW + h * DKV + dp * 2] = acc;
    }
}

// ============================================================
// context2 = matrix @ vp2 -> ctx cols [256, 288). tile 32 rows.
// grid (16 row-tiles, 16 batches), 256 threads.
// ============================================================
__global__ __launch_bounds__(256) void ctx2_kernel(
    const float* __restrict__ matrix, const float* __restrict__ vp2, float* __restrict__ ctx)
{
    __shared__ __align__(16) float  Ms[32][68];
    __shared__ __align__(16) float2 Vs[64][17];
    const int b = blockIdx.y, i0 = blockIdx.x * 32;
    const int tid = threadIdx.x;
    const int r = tid >> 3, cq = tid & 7;

    float2 acc0 = make_float2(0.f, 0.f), acc1 = make_float2(0.f, 0.f);
    for (int k0 = 0; k0 < SS; k0 += 64) {
#pragma unroll
        for (int t = 0; t < 2; t++) {
            int idx = tid + t * 256;            // 512 float4 slots: 32 rows x 16
            int row = idx >> 4, c4 = idx & 15;
            *(float4*)&Ms[row][c4 * 4] =
                *(const float4*)&matrix[((size_t)(b * SS + i0 + row)) * SS + k0 + c4 * 4];
        }
#pragma unroll
        for (int t = 0; t < 4; t++) {
            int idx = tid + t * 256, kk = idx >> 4, dp = idx & 15;
            Vs[kk][dp] = *(const float2*)&vp2[((size_t)(b * SS + k0 + kk)) * DKV + dp * 2];
        }
        __syncthreads();
#pragma unroll
        for (int kk = 0; kk < 64; kk++) {
            float a = Ms[r][kk];
            float2 a2 = {a, a};
            ffma2(acc0, a2, Vs[kk][cq * 2]);
            ffma2(acc1, a2, Vs[kk][cq * 2 + 1]);
        }
        __syncthreads();
    }
    float4 o4 = {acc0.x, acc0.y, acc1.x, acc1.y};
    *(float4*)&ctx[((size_t)(b * SS + i0 + r)) * CTXW + HH * DKV + cq * 4] = o4;
}

// ============================================================
// Gate: per (b,i,j): v = [matrix[b,j,i], attn[b,:,j,i]] (9 ch),
// LN -> relu(9->6) -> sigmoid(6->1); matrix_out = matrix * g
// ============================================================
__global__ __launch_bounds__(256) void gate_kernel(
    const float* __restrict__ attn, const float* __restrict__ matrix, float* __restrict__ mout,
    const float* __restrict__ fu_ln_g, const float* __restrict__ fu_ln_b,
    const float* __restrict__ fu_w1, const float* __restrict__ fu_b1,
    const float* __restrict__ fu_w2, const float* __restrict__ fu_b2)
{
    __shared__ float pl[9][32][33];
    __shared__ float pg[9], pb[9], w1[9][6], b1[6], w2[6], b2s;

    int b = blockIdx.z;
    int i0 = blockIdx.y * 32, j0 = blockIdx.x * 32;
    int tid = threadIdx.x;

    if (tid < 9) { pg[tid] = fu_ln_g[tid]; pb[tid] = fu_ln_b[tid]; }
    if (tid >= 32 && tid < 86) { int t = tid - 32; w1[t / 6][t % 6] = fu_w1[t]; }
    if (tid >= 96 && tid < 102) b1[tid - 96] = fu_b1[tid - 96];
    if (tid >= 128 && tid < 134) w2[tid - 128] = fu_w2[tid - 128];
    if (tid == 160) b2s = fu_b2[0];

    for (int c = 0; c < 9; c++) {
        const float* src = (c == 0) ? (matrix + (long long)b * SS * SS)
                                    : (attn + ((long long)(b * HH + c - 1)) * SS * SS);
        for (int i = tid; i < 1024; i += 256) {
            int jj = i >> 5, ii = i & 31;
            pl[c][jj][ii] = src[(long long)(j0 + jj) * SS + i0 + ii];
        }
    }
    __syncthreads();

#pragma unroll
    for (int r = 0; r < 4; r++) {
        int idx = tid + r * 256;
        int ii = idx >> 5, jj = idx & 31;
        float v[9];
        float m = 0.f;
#pragma unroll
        for (int c = 0; c < 9; c++) { v[c] = pl[c][jj][ii]; m += v[c]; }
        m *= (1.f / 9.f);
        float var = 0.f;
#pragma unroll
        for (int c = 0; c < 9; c++) { float dd = v[c] - m; var += dd * dd; }
        var *= (1.f / 9.f);
        float rinv = rsqrtf(var + EPS);
        float y[9];
#pragma unroll
        for (int c = 0; c < 9; c++) y[c] = pg[c] * (v[c] - m) * rinv + pb[c];
        float z = b2s;
#pragma unroll
        for (int j = 0; j < 6; j++) {
            float t = b1[j];
#pragma unroll
            for (int c = 0; c < 9; c++) t += y[c] * w1[c][j];
            t = fmaxf(t, 0.f);
            z += t * w2[j];
        }
        float g = 1.f / (1.f + __expf(-z));
        long long o = ((long long)b * SS + i0 + ii) * SS + j0 + jj;
        mout[o] = matrix[o] * g;
    }
}

// ============================================================
// Final layernorm over 256 channels: one block per row
// ============================================================
__global__ __launch_bounds__(256) void ln_kernel(
    const float* __restrict__ x, const float* __restrict__ g,
    const float* __restrict__ bt, float* __restrict__ out)
{
    int row = blockIdx.x, tid = threadIdx.x;
    float v = x[(long long)row * DM + tid];

    __shared__ float red[8];
    float s = v;
#pragma unroll
    for (int o = 16; o; o >>= 1) s += __shfl_xor_sync(0xffffffffu, s, o);
    if ((tid & 31) == 0) red[tid >> 5] = s;
    __syncthreads();
    float tot = 0.f;
#pragma unroll
    for (int i = 0; i < 8; i++) tot += red[i];
    float m = tot * (1.f / DM);
    __syncthreads();

    float d = v - m;
    float s2 = d * d;
#pragma unroll
    for (int o = 16; o; o >>= 1) s2 += __shfl_xor_sync(0xffffffffu, s2, o);
    if ((tid & 31) == 0) red[tid >> 5] = s2;
    __syncthreads();
    float vtot = 0.f;
#pragma unroll
    for (int i = 0; i < 8; i++) vtot += red[i];
    float var = vtot * (1.f / DM);

    out[(long long)row * DM + tid] = g[tid] * d * rsqrtf(var + EPS) + bt[tid];
}

// ============================================================
extern "C" void kernel_launch(void* const* d_in, const int* in_sizes, int n_in,
                              void* d_out, int out_size)
{
    const float* inQ    = (const float*)d_in[0];
    const float* inK    = (const float*)d_in[1];
    const float* inV    = (const float*)d_in[2];
    const int*   mask   = (const int*)  d_in[3];
    const float* matrix = (const float*)d_in[4];
    const float* W_Q    = (const float*)d_in[5];
    const float* W_K    = (const float*)d_in[6];
    const float* W_V    = (const float*)d_in[7];
    const float* W_V2   = (const float*)d_in[8];
    const float* W_fc   = (const float*)d_in[9];
    const float* ln_g   = (const float*)d_in[10];
    const float* ln_b   = (const float*)d_in[11];
    const float* fu_ln_g= (const float*)d_in[12];
    const float* fu_ln_b= (const float*)d_in[13];
    const float* fu_w1  = (const float*)d_in[14];
    const float* fu_b1  = (const float*)d_in[15];
    const float* fu_w2  = (const float*)d_in[16];
    const float* fu_b2  = (const float*)d_in[17];

    float* out  = (float*)d_out;                            // [B,S,DM]
    float* mout = (float*)d_out + (long long)BB * SS * DM;  // [B,S,S]

    float *pQ, *pK, *pV, *pattn, *pvp2, *pctx, *pfc;
    cudaGetSymbolAddress((void**)&pQ, g_Q);
    cudaGetSymbolAddress((void**)&pK, g_K);
    cudaGetSymbolAddress((void**)&pV, g_V);
    cudaGetSymbolAddress((void**)&pattn, g_attn);
    cudaGetSymbolAddress((void**)&pvp2, g_vp2);
    cudaGetSymbolAddress((void**)&pctx, g_ctx);
    cudaGetSymbolAddress((void**)&pfc, g_fc);

    // QKV projections: [8192,256] @ [256,256], tile 128x64 -> grid (4,64)
    sgemm2_kernel<<<dim3(4, 64), 256>>>(inQ, W_Q, pQ, DM, DM, DM, DM);
    sgemm2_kernel<<<dim3(4, 64), 256>>>(inK, W_K, pK, DM, DM, DM, DM);
    sgemm2_kernel<<<dim3(4, 64), 256>>>(inV, W_V, pV, DM, DM, DM, DM);
    // vp2 = input_V @ W_V2 : [8192,256] @ [256,32]
    sgemm_n32_kernel<<<dim3(1, 64), 256>>>(inV, W_V2, pvp2, DM, DM);

    // fused attention (writes attn + ctx cols 0..255)
    attn2_kernel<<<dim3(SS / 16, HH, BB), 256>>>(pQ, pK, pV, mask, pattn, pctx);

    // context2 = matrix @ vp2 -> ctx cols 256..287
    ctx2_kernel<<<dim3(16, BB), 256>>>(matrix, pvp2, pctx);

    // gate -> matrix_out
    gate_kernel<<<dim3(SS / 32, SS / 32, BB), 256>>>(pattn, matrix, mout,
                                                     fu_ln_g, fu_ln_b, fu_w1, fu_b1, fu_w2, fu_b2);

    // fc: [8192,288] @ [288,256]
    sgemm2_kernel<<<dim3(4, 64), 256>>>(pctx, W_fc, pfc, CTXW, CTXW, DM, DM);

    // final layernorm -> output
    ln_kernel<<<BB * SS, 256>>>(pfc, ln_g, ln_b, out);
}